// round 15
// baseline (speedup 1.0000x reference)
#include <cuda_runtime.h>

#define NN 50000
#define NE 400000
#define NG2 391       // node groups of 128 for the tail scan

// ---------------- scratch (device globals) ----------------
__device__ float g_Z1[NN*256];
__device__ float g_H1[NN*128];
__device__ float g_Z2[NN*128];
__device__ float g_H2[NN*64];
__device__ float g_CONHS[(NN+1)*64];    // conh shifted: row n+1 = conh[n], row 0 = 0
__device__ float g_A2[(size_t)NN*320];  // [u_h0..u_h3 (256) | conh_shift (64)]
__device__ float g_HM[NN*256];
__device__ float g_AUX[NG2*256];
__device__ float g_el1[NN], g_er1[NN], g_el2[NN], g_er2[NN];
__device__ float g_elm[NN*4], g_erm[NN*4];
// pre-split interleaved (hi,lo) weights
__device__ float g_W1s[256*128];   // [256 out][2*64]   rows <128: W1a, >=128: W1b
__device__ float g_W2s[128*256];   // [128 out][2*128]  rows <64: W2a, >=64: W2b
__device__ float g_B3s[256*256];   // [256 out][2*128]  k<64: Wma, k>=64: Wmb
__device__ float g_wml[256], g_wmr[256];   // per-head Wma_h^T @ alma_h / arma_h
__device__ float g_biasm[256];
__device__ int g_cnt[NN];
__device__ int g_off[NN+1];
__device__ int g_pos[NN];
__device__ int g_csrc[NE];
__device__ int g_gaux[256];

// ---------------- helpers ----------------
__device__ __forceinline__ float lrelu_exp(float v) {
    v = (v >= 0.f) ? v : 0.2f*v;
    return __expf(v);
}
__device__ __forceinline__ float tf32_rna(float x) {
    unsigned r;
    asm("cvt.rna.tf32.f32 %0, %1;" : "=r"(r) : "f"(x));
    return __uint_as_float(r);
}
__device__ __forceinline__ void mma_tf32(float* c,
                                         unsigned a0, unsigned a1, unsigned a2, unsigned a3,
                                         unsigned b0, unsigned b1) {
    asm volatile("mma.sync.aligned.m16n8k8.row.col.f32.tf32.tf32.f32 "
                 "{%0,%1,%2,%3},{%4,%5,%6,%7},{%8,%9},{%0,%1,%2,%3};"
                 : "+f"(c[0]), "+f"(c[1]), "+f"(c[2]), "+f"(c[3])
                 : "r"(a0), "r"(a1), "r"(a2), "r"(a3), "r"(b0), "r"(b1));
}

// ---------------- weight pack ----------------
__global__ void pack_w_kernel(const float* __restrict__ W1a, const float* __restrict__ W1b,
                              const float* __restrict__ W2a, const float* __restrict__ W2b,
                              const float* __restrict__ Wma, const float* __restrict__ Wmb,
                              const float* __restrict__ alma, const float* __restrict__ arma,
                              const float* __restrict__ bma, const float* __restrict__ bmb) {
    int i = blockIdx.x*blockDim.x + threadIdx.x;
    if (i < 256*64) {
        int r = i >> 6, k = i & 63;
        float w = (r < 128) ? W1a[i] : W1b[i - 128*64];
        float h = tf32_rna(w);
        g_W1s[r*128 + 2*k] = h; g_W1s[r*128 + 2*k + 1] = w - h;
    }
    if (i < 128*128) {
        int r = i >> 7, k = i & 127;
        float w = (r < 64) ? W2a[r*128 + k] : W2b[(r-64)*128 + k];
        float h = tf32_rna(w);
        g_W2s[r*256 + 2*k] = h; g_W2s[r*256 + 2*k + 1] = w - h;
    }
    if (i < 256*128) {
        int r = i >> 7, k = i & 127;
        float w = (k < 64) ? Wma[r*64 + k] : Wmb[r*64 + (k - 64)];
        float h = tf32_rna(w);
        g_B3s[r*256 + 2*k] = h; g_B3s[r*256 + 2*k + 1] = w - h;
    }
    if (i < 256) {
        int h = i >> 6, j = i & 63;
        float sl = 0.f, sr = 0.f;
        for (int c = 0; c < 64; c++) {
            float w = Wma[(h*64 + c)*64 + j];
            sl += alma[h*64 + c]*w; sr += arma[h*64 + c]*w;
        }
        g_wml[i] = sl; g_wmr[i] = sr;
        g_biasm[i] = bma[i] + bmb[i];
    }
}

// ---------------- CSR build ----------------
__global__ void zero_cnt_kernel() {
    int i = blockIdx.x*blockDim.x + threadIdx.x;
    if (i < NN) g_cnt[i] = 0;
}
__global__ void hist_kernel(const int* __restrict__ dst) {
    int e = blockIdx.x*blockDim.x + threadIdx.x;
    if (e < NE) atomicAdd(&g_cnt[dst[e]], 1);
}
__global__ void csr_scan1_kernel() {
    __shared__ int ws[8];
    int g = blockIdx.x, t = threadIdx.x;
    int i = g*256 + t;
    int lane = t & 31, wid = t >> 5;
    int v = (i < NN) ? g_cnt[i] : 0;
    int s = v;
#pragma unroll
    for (int o = 1; o < 32; o <<= 1) {
        int q = __shfl_up_sync(0xffffffffu, s, o);
        if (lane >= o) s += q;
    }
    if (lane == 31) ws[wid] = s;
    __syncthreads();
    if (wid == 0) {
        int w = (lane < 8) ? ws[lane] : 0;
#pragma unroll
        for (int o = 1; o < 8; o <<= 1) {
            int q = __shfl_up_sync(0xffffffffu, w, o);
            if (lane >= o) w += q;
        }
        if (lane < 8) ws[lane] = w;
    }
    __syncthreads();
    int excl = (wid > 0 ? ws[wid-1] : 0) + (s - v);
    if (i < NN) g_off[i] = excl;
    if (t == 0) g_gaux[g] = ws[7];
}
__global__ void csr_scan2_kernel() {
    __shared__ int ws[8];
    int t = threadIdx.x;
    int lane = t & 31, wid = t >> 5;
    int v = (t < 196) ? g_gaux[t] : 0;
    int s = v;
#pragma unroll
    for (int o = 1; o < 32; o <<= 1) {
        int q = __shfl_up_sync(0xffffffffu, s, o);
        if (lane >= o) s += q;
    }
    if (lane == 31) ws[wid] = s;
    __syncthreads();
    if (wid == 0) {
        int w = (lane < 8) ? ws[lane] : 0;
#pragma unroll
        for (int o = 1; o < 8; o <<= 1) {
            int q = __shfl_up_sync(0xffffffffu, w, o);
            if (lane >= o) w += q;
        }
        if (lane < 8) ws[lane] = w;
    }
    __syncthreads();
    int excl = (wid > 0 ? ws[wid-1] : 0) + (s - v);
    if (t < 196) g_gaux[t] = excl;
}
__global__ void csr_apply_kernel() {
    int g = blockIdx.x, t = threadIdx.x;
    int i = g*256 + t;
    if (i < NN) {
        int o = g_off[i] + g_gaux[g];
        g_off[i] = o;
        g_pos[i] = o;
    }
    if (g == 0 && t == 0) g_off[NN] = NE;
}
__global__ void scatter_csr_kernel(const int* __restrict__ src, const int* __restrict__ dst) {
    int e = blockIdx.x*blockDim.x + threadIdx.x;
    if (e >= NE) return;
    int p = atomicAdd(&g_pos[dst[e]], 1);
    g_csrc[p] = src[e];
}

// ---------------- 3xTF32 tensor-core GEMM (validated template) ----------------
#define GKC 16
#define GLDS 136

template<int NT>
__global__ __launch_bounds__(256, 2)
void gemm_kernel(const float* __restrict__ A, int lda, int aSplit, int aCol1,
                 const float* __restrict__ Bs,
                 float* __restrict__ C, int ldc, int M, int K,
                 const float* __restrict__ bias,
                 int adimTotal, int hshift, int H,
                 const float* __restrict__ al, const float* __restrict__ ar,
                 float* __restrict__ el, float* __restrict__ er) {
    __shared__ float Ahi[GKC][GLDS];
    __shared__ float Alo[GKC][GLDS];
    __shared__ float Bhi[GKC][GLDS];
    __shared__ float Blo[GKC][GLDS];
    __shared__ float epiel[2][128];
    __shared__ float epier[2][128];

    int tid = threadIdx.x;
    int bm = blockIdx.y * 128;
    int bn = blockIdx.x * (NT*16);
    int w = tid >> 5;
    int lane = tid & 31;
    int warpM = w & 3;
    int warpN = w >> 2;
    int g  = lane >> 2;
    int tg = lane & 3;
    int acb = (aSplit < K) ? bn : 0;

    float acc[2][NT][4];
#pragma unroll
    for (int mt = 0; mt < 2; mt++)
#pragma unroll
        for (int nt = 0; nt < NT; nt++)
#pragma unroll
            for (int q = 0; q < 4; q++) acc[mt][nt][q] = 0.f;

    int ntiles = K / GKC;
    for (int kt = 0; kt < ntiles; kt++) {
        int koff = kt * GKC;
        int acolt = (koff < aSplit) ? (acb + koff) : (aCol1 + koff - aSplit);
#pragma unroll
        for (int ii = 0; ii < 2; ii++) {
            int i = tid + ii*256;
            int row = i >> 2;
            int tgp = i & 3;
            int k4  = tgp << 2;
            int rsw = row ^ (tgp << 3);
            float4 va = make_float4(0.f,0.f,0.f,0.f);
            int gr = bm + row;
            if (gr < M) va = *(const float4*)(A + (size_t)gr*lda + acolt + k4);
            const float* brow = Bs + (size_t)(bn + (row & (NT*16 - 1)))*2*K + 2*(koff + k4);
            float4 vb0 = *(const float4*)(brow);
            float4 vb1 = *(const float4*)(brow + 4);
            float h;
            h = tf32_rna(va.x); Ahi[k4+0][rsw] = h; Alo[k4+0][rsw] = va.x - h;
            h = tf32_rna(va.y); Ahi[k4+1][rsw] = h; Alo[k4+1][rsw] = va.y - h;
            h = tf32_rna(va.z); Ahi[k4+2][rsw] = h; Alo[k4+2][rsw] = va.z - h;
            h = tf32_rna(va.w); Ahi[k4+3][rsw] = h; Alo[k4+3][rsw] = va.w - h;
            Bhi[k4+0][rsw] = vb0.x; Blo[k4+0][rsw] = vb0.y;
            Bhi[k4+1][rsw] = vb0.z; Blo[k4+1][rsw] = vb0.w;
            Bhi[k4+2][rsw] = vb1.x; Blo[k4+2][rsw] = vb1.y;
            Bhi[k4+3][rsw] = vb1.z; Blo[k4+3][rsw] = vb1.w;
        }
        __syncthreads();

#pragma unroll
        for (int k8 = 0; k8 < GKC/8; k8++) {
            int kb = k8*8;
            int k0 = kb + tg;
            int k1 = kb + tg + 4;
            int sw0 = (((kb >> 2)    ) & 3) << 3;
            int sw1 = (((kb >> 2) + 1) & 3) << 3;
            unsigned ah[2][4], alr[2][4];
#pragma unroll
            for (int mt = 0; mt < 2; mt++) {
                int rb = warpM*32 + mt*16;
                int r0 = (rb + g)     ^ sw0;
                int r8 = (rb + g + 8) ^ sw0;
                int q0 = (rb + g)     ^ sw1;
                int q8 = (rb + g + 8) ^ sw1;
                ah[mt][0] = __float_as_uint(Ahi[k0][r0]);
                ah[mt][1] = __float_as_uint(Ahi[k0][r8]);
                ah[mt][2] = __float_as_uint(Ahi[k1][q0]);
                ah[mt][3] = __float_as_uint(Ahi[k1][q8]);
                alr[mt][0] = __float_as_uint(Alo[k0][r0]);
                alr[mt][1] = __float_as_uint(Alo[k0][r8]);
                alr[mt][2] = __float_as_uint(Alo[k1][q0]);
                alr[mt][3] = __float_as_uint(Alo[k1][q8]);
            }
#pragma unroll
            for (int nt = 0; nt < NT; nt++) {
                int nb = warpN*(NT*8) + nt*8;
                int n0 = (nb + g) ^ sw0;
                int n1 = (nb + g) ^ sw1;
                unsigned bh0 = __float_as_uint(Bhi[k0][n0]);
                unsigned bh1 = __float_as_uint(Bhi[k1][n1]);
                unsigned bl0 = __float_as_uint(Blo[k0][n0]);
                unsigned bl1 = __float_as_uint(Blo[k1][n1]);
#pragma unroll
                for (int mt = 0; mt < 2; mt++) {
                    mma_tf32(acc[mt][nt], ah[mt][0], ah[mt][1], ah[mt][2], ah[mt][3], bh0, bh1);
                    mma_tf32(acc[mt][nt], ah[mt][0], ah[mt][1], ah[mt][2], ah[mt][3], bl0, bl1);
                    mma_tf32(acc[mt][nt], alr[mt][0], alr[mt][1], alr[mt][2], alr[mt][3], bh0, bh1);
                }
            }
        }
        __syncthreads();
    }

    bool awarp = (el != nullptr) && (bn + warpN*(NT*8)) < adimTotal;
    float pel[2][2] = {{0.f,0.f},{0.f,0.f}};
    float per_[2][2] = {{0.f,0.f},{0.f,0.f}};
#pragma unroll
    for (int mt = 0; mt < 2; mt++) {
        int r0 = bm + warpM*32 + mt*16 + g;
#pragma unroll
        for (int nt = 0; nt < NT; nt++) {
            int gc = bn + warpN*(NT*8) + nt*8 + tg*2;
            float c0 = acc[mt][nt][0], c1 = acc[mt][nt][1];
            float c2 = acc[mt][nt][2], c3 = acc[mt][nt][3];
            if (bias) {
                float b0 = bias[gc], b1v = bias[gc+1];
                c0 = 0.5f*(c0 + b0); c1 = 0.5f*(c1 + b1v);
                c2 = 0.5f*(c2 + b0); c3 = 0.5f*(c3 + b1v);
            }
            if (r0 < M)     *(float2*)(C + (size_t)r0*ldc + gc)     = make_float2(c0, c1);
            if (r0+8 < M)   *(float2*)(C + (size_t)(r0+8)*ldc + gc) = make_float2(c2, c3);
            if (awarp) {
                float w0 = al[gc], w1 = al[gc+1];
                float u0 = ar[gc], u1 = ar[gc+1];
                pel[mt][0] += c0*w0 + c1*w1;
                pel[mt][1] += c2*w0 + c3*w1;
                per_[mt][0] += c0*u0 + c1*u1;
                per_[mt][1] += c2*u0 + c3*u1;
            }
        }
    }
    if (el != nullptr) {
#pragma unroll
        for (int mt = 0; mt < 2; mt++)
#pragma unroll
            for (int rp = 0; rp < 2; rp++) {
#pragma unroll
                for (int o = 1; o <= 2; o <<= 1) {
                    pel[mt][rp]  += __shfl_xor_sync(0xffffffffu, pel[mt][rp],  o);
                    per_[mt][rp] += __shfl_xor_sync(0xffffffffu, per_[mt][rp], o);
                }
                if (tg == 0) {
                    int row = warpM*32 + mt*16 + g + rp*8;
                    epiel[warpN][row] = pel[mt][rp];
                    epier[warpN][row] = per_[mt][rp];
                }
            }
        __syncthreads();
        if (tid < 128) {
            int row = tid;
            int gr = bm + row;
            if (gr < M) {
#pragma unroll
                for (int wn = 0; wn < 2; wn++) {
                    int cb = bn + wn*(NT*8);
                    if (cb < adimTotal && ((cb & ((1<<hshift)-1)) == 0)) {
                        int h = cb >> hshift;
                        el[(size_t)gr*H + h] = epiel[wn][row] + ((NT*8 < (1<<hshift)) ? epiel[wn+1][row] : 0.f);
                        er[(size_t)gr*H + h] = epier[wn][row] + ((NT*8 < (1<<hshift)) ? epier[wn+1][row] : 0.f);
                    }
                }
            }
        }
    }
}

// ---------------- CSR aggregation (H=1) with fused finalize (R12) ----------------
template<int D4>
__global__ void agg1_kernel(const float* __restrict__ el, const float* __restrict__ er,
                            const float4* __restrict__ Z4, int ldz4,
                            const float* __restrict__ ba, const float* __restrict__ bb,
                            float4* __restrict__ out4) {
    int t = blockIdx.x*blockDim.x + threadIdx.x;
    int n = t / D4;
    int j = t - n*D4;
    if (n >= NN) return;
    int o0 = g_off[n], o1 = g_off[n+1];
    float ern = er[n];
    float4 acc = make_float4(0.f,0.f,0.f,0.f);
    float den = 0.f;
    for (int p = o0; p < o1; p++) {
        int s = g_csrc[p];
        float ee = lrelu_exp(el[s] + ern);
        den += ee;
        float4 z = Z4[(size_t)s*ldz4 + j];
        acc.x += ee*z.x; acc.y += ee*z.y; acc.z += ee*z.z; acc.w += ee*z.w;
    }
    float inv = (o1 > o0) ? 1.f/den : 0.f;
    float4 b1 = ((const float4*)ba)[j];
    float4 b2 = ((const float4*)bb)[j];
    float4 r;
    r.x = acc.x*inv + b1.x + b2.x;
    r.y = acc.y*inv + b1.y + b2.y;
    r.z = acc.z*inv + b1.z + b2.z;
    r.w = acc.w*inv + b1.w + b2.w;
    if (n > 0) {
        float4 zb = Z4[(size_t)(n-1)*ldz4 + D4 + j];
        r.x += zb.x; r.y += zb.y; r.z += zb.z; r.w += zb.w;
    }
    out4[(size_t)n*D4 + j] = make_float4(0.5f*r.x, 0.5f*r.y, 0.5f*r.z, 0.5f*r.w);
}

// ---------------- chain pass + fused MH dots ----------------
__global__ void chain_norm_shift_dots_kernel(const float* __restrict__ Hin,
                                             float* __restrict__ outs,
                                             const float* __restrict__ wml,
                                             const float* __restrict__ wmr,
                                             float* __restrict__ elm,
                                             float* __restrict__ erm) {
    int w = (blockIdx.x*blockDim.x + threadIdx.x) >> 5;
    int lane = threadIdx.x & 31;
    if (w >= NN) return;
    int n = w;
    int base = n*64 + lane*2;
    float d0 = 0.f, d1 = 0.f;
    if (n > 0) {
        d0 = Hin[base - 64]     - Hin[base];
        d1 = Hin[base - 64 + 1] - Hin[base + 1];
    }
    float ss = d0*d0 + d1*d1;
#pragma unroll
    for (int o = 16; o; o >>= 1) ss += __shfl_xor_sync(0xffffffffu, ss, o);
    float inv = 1.f/(sqrtf(ss) + 1e-7f);
    float c0 = d0*inv, c1 = d1*inv;
    outs[base + 64]     = c0;
    outs[base + 64 + 1] = c1;
    if (n == 0) { outs[lane*2] = 0.f; outs[lane*2 + 1] = 0.f; }
#pragma unroll
    for (int h = 0; h < 4; h++) {
        float2 wl = *(const float2*)&wml[h*64 + lane*2];
        float2 wr = *(const float2*)&wmr[h*64 + lane*2];
        float sl = c0*wl.x + c1*wl.y;
        float sr = c0*wr.x + c1*wr.y;
#pragma unroll
        for (int o = 16; o; o >>= 1) {
            sl += __shfl_xor_sync(0xffffffffu, sl, o);
            sr += __shfl_xor_sync(0xffffffffu, sr, o);
        }
        if (lane == 0) { elm[n*4 + h] = sl; erm[n*4 + h] = sr; }
    }
}

// ---------------- input-space MH aggregation (LEAN: exp computed once per head, broadcast) ----
__global__ void aggmhx_kernel(const float* __restrict__ el, const float* __restrict__ er,
                              const float2* __restrict__ c2, float* __restrict__ A2) {
    int w = (blockIdx.x*blockDim.x + threadIdx.x) >> 5;
    int lane = threadIdx.x & 31;
    if (w >= NN) return;
    int n = w;
    int o0 = g_off[n], o1 = g_off[n+1];
    // lane h (<4) owns head h's er
    float erh = (lane < 4) ? er[n*4 + lane] : 0.f;
    float ax0 = 0.f, ay0 = 0.f, ax1 = 0.f, ay1 = 0.f;
    float ax2 = 0.f, ay2 = 0.f, ax3 = 0.f, ay3 = 0.f;
    float den0 = 0.f, den1 = 0.f, den2 = 0.f, den3 = 0.f;
    for (int p = o0; p < o1; p++) {
        int s = g_csrc[p];
        // lanes 0-3 compute their head's exp (4 MUFU total per edge)
        float ex = 0.f;
        if (lane < 4) ex = lrelu_exp(el[s*4 + lane] + erh);
        float e0 = __shfl_sync(0xffffffffu, ex, 0);
        float e1 = __shfl_sync(0xffffffffu, ex, 1);
        float e2 = __shfl_sync(0xffffffffu, ex, 2);
        float e3 = __shfl_sync(0xffffffffu, ex, 3);
        float2 cv = c2[(size_t)(s+1)*32 + lane];
        den0 += e0; den1 += e1; den2 += e2; den3 += e3;
        ax0 += e0*cv.x; ay0 += e0*cv.y;
        ax1 += e1*cv.x; ay1 += e1*cv.y;
        ax2 += e2*cv.x; ay2 += e2*cv.y;
        ax3 += e3*cv.x; ay3 += e3*cv.y;
    }
    bool has = (o1 > o0);
    float i0 = has ? 1.f/den0 : 0.f;
    float i1 = has ? 1.f/den1 : 0.f;
    float i2 = has ? 1.f/den2 : 0.f;
    float i3 = has ? 1.f/den3 : 0.f;
    size_t rb = (size_t)n*320 + lane*2;
    *(float2*)&A2[rb]       = make_float2(ax0*i0, ay0*i0);
    *(float2*)&A2[rb + 64]  = make_float2(ax1*i1, ay1*i1);
    *(float2*)&A2[rb + 128] = make_float2(ax2*i2, ay2*i2);
    *(float2*)&A2[rb + 192] = make_float2(ax3*i3, ay3*i3);
    float2 cb = c2[(size_t)n*32 + lane];
    *(float2*)&A2[rb + 256] = cb;
}

// ---------------- fused tail ----------------
__global__ __launch_bounds__(128)
void dsscan_local_kernel(const float* __restrict__ HM, float* __restrict__ out) {
    int g = blockIdx.x;
    int t = threadIdx.x, wid = t >> 5, lane = t & 31;
    int c = wid*64 + lane*2;
    int start = g*128;
    int end = min(start+128, NN);
    const float2* H2p = (const float2*)HM;
    float2* out2 = (float2*)out;
    int ci = c >> 1;
    float2 prev = (start > 0) ? H2p[(size_t)(start-1)*128 + ci] : make_float2(0.f,0.f);
    float2 cur  = H2p[(size_t)start*128 + ci];
    float rx = 0.f, ry = 0.f;
    for (int n = start; n < end; n++) {
        float2 nxt = (n+1 < end) ? H2p[(size_t)(n+1)*128 + ci] : make_float2(0.f,0.f);
        float d0 = 0.f, d1 = 0.f;
        if (n > 0) { d0 = prev.x - cur.x; d1 = prev.y - cur.y; }
        float ss = d0*d0 + d1*d1;
#pragma unroll
        for (int o = 16; o; o >>= 1) ss += __shfl_xor_sync(0xffffffffu, ss, o);
        float inv = 1.f/(sqrtf(ss) + 1e-7f);
        rx += d0*inv; ry += d1*inv;
        out2[(size_t)n*128 + ci] = make_float2(rx, ry);
        prev = cur; cur = nxt;
    }
    ((float2*)g_AUX)[g*128 + ci] = make_float2(rx, ry);
}
__global__ void aux_scan_kernel() {
    __shared__ float ws[16];
    int c = blockIdx.x;
    int t = threadIdx.x;
    int lane = t & 31, wid = t >> 5;
    float v = (t < NG2) ? g_AUX[t*256 + c] : 0.f;
    float s = v;
#pragma unroll
    for (int o = 1; o < 32; o <<= 1) {
        float q = __shfl_up_sync(0xffffffffu, s, o);
        if (lane >= o) s += q;
    }
    if (lane == 31) ws[wid] = s;
    __syncthreads();
    if (wid == 0) {
        float w = (lane < 16) ? ws[lane] : 0.f;
#pragma unroll
        for (int o = 1; o < 16; o <<= 1) {
            float q = __shfl_up_sync(0xffffffffu, w, o);
            if (lane >= o) w += q;
        }
        if (lane < 16) ws[lane] = w;
    }
    __syncthreads();
    float excl = (wid > 0 ? ws[wid-1] : 0.f) + (s - v);
    if (t < NG2) g_AUX[t*256 + c] = excl;
}
__global__ void add_off_kernel(float* __restrict__ out) {
    int i = blockIdx.x*blockDim.x + threadIdx.x;
    if (i >= NN*64) return;
    int n = i >> 6, c4 = i & 63;
    int g = n >> 7;
    float4 o = ((float4*)out)[i];
    float4 a = ((const float4*)g_AUX)[g*64 + c4];
    o.x += a.x; o.y += a.y; o.z += a.z; o.w += a.w;
    ((float4*)out)[i] = o;
}

// ---------------- host orchestration ----------------
extern "C" void kernel_launch(void* const* d_in, const int* in_sizes, int n_in,
                              void* d_out, int out_size) {
    const float* x    = (const float*)d_in[0];
    const int*   src0 = (const int*)d_in[1];
    const int*   dst0 = (const int*)d_in[2];
    const float* W1a  = (const float*)d_in[5];
    const float* al1a = (const float*)d_in[6];
    const float* ar1a = (const float*)d_in[7];
    const float* b1a  = (const float*)d_in[8];
    const float* W1b  = (const float*)d_in[9];
    const float* b1b  = (const float*)d_in[12];
    const float* W2a  = (const float*)d_in[13];
    const float* al2a = (const float*)d_in[14];
    const float* ar2a = (const float*)d_in[15];
    const float* b2a  = (const float*)d_in[16];
    const float* W2b  = (const float*)d_in[17];
    const float* b2b  = (const float*)d_in[20];
    const float* Wma  = (const float*)d_in[21];
    const float* alma = (const float*)d_in[22];
    const float* arma = (const float*)d_in[23];
    const float* bma  = (const float*)d_in[24];
    const float* Wmb  = (const float*)d_in[25];
    const float* bmb  = (const float*)d_in[28];
    float* out = (float*)d_out;

    float *pZ1,*pH1,*pZ2,*pH2,*pCONHS,*pA2,*pHM;
    float *pel1,*per1,*pel2,*per2,*pelm,*perm;
    float *pW1s,*pW2s,*pB3s,*pwml,*pwmr,*pbiasm;
    cudaGetSymbolAddress((void**)&pZ1,   g_Z1);
    cudaGetSymbolAddress((void**)&pH1,   g_H1);
    cudaGetSymbolAddress((void**)&pZ2,   g_Z2);
    cudaGetSymbolAddress((void**)&pH2,   g_H2);
    cudaGetSymbolAddress((void**)&pCONHS,g_CONHS);
    cudaGetSymbolAddress((void**)&pA2,   g_A2);
    cudaGetSymbolAddress((void**)&pHM,   g_HM);
    cudaGetSymbolAddress((void**)&pel1,  g_el1);
    cudaGetSymbolAddress((void**)&per1,  g_er1);
    cudaGetSymbolAddress((void**)&pel2,  g_el2);
    cudaGetSymbolAddress((void**)&per2,  g_er2);
    cudaGetSymbolAddress((void**)&pelm,  g_elm);
    cudaGetSymbolAddress((void**)&perm,  g_erm);
    cudaGetSymbolAddress((void**)&pW1s,  g_W1s);
    cudaGetSymbolAddress((void**)&pW2s,  g_W2s);
    cudaGetSymbolAddress((void**)&pB3s,  g_B3s);
    cudaGetSymbolAddress((void**)&pwml,  g_wml);
    cudaGetSymbolAddress((void**)&pwmr,  g_wmr);
    cudaGetSymbolAddress((void**)&pbiasm,g_biasm);

    // launch order: ncu capture window (4th launch) hits gemm1
    pack_w_kernel<<<128, 256>>>(W1a, W1b, W2a, W2b, Wma, Wmb, alma, arma, bma, bmb);
    zero_cnt_kernel<<<(NN + 255)/256, 256>>>();
    hist_kernel<<<(NE + 255)/256, 256>>>(dst0);

    // ---- layer 1 GEMM (R12 config: A=x K=64, N=256, fused dots) ----
    gemm_kernel<8><<<dim3(2, 391), 256>>>(x, 64, 64, 0, pW1s, pZ1, 256, NN, 64,
                                          nullptr, 128, 7, 1, al1a, ar1a, pel1, per1);

    // ---- CSR build ----
    csr_scan1_kernel<<<196, 256>>>();
    csr_scan2_kernel<<<1, 256>>>();
    csr_apply_kernel<<<196, 256>>>();
    scatter_csr_kernel<<<(NE + 255)/256, 256>>>(src0, dst0);

    agg1_kernel<32><<<6250, 256>>>(pel1, per1, (const float4*)pZ1, 64, b1a, b1b, (float4*)pH1);

    // ---- layer 2 (R12 config) ----
    gemm_kernel<8><<<dim3(1, 391), 256>>>(pH1, 128, 128, 0, pW2s, pZ2, 128, NN, 128,
                                          nullptr, 64, 6, 1, al2a, ar2a, pel2, per2);
    agg1_kernel<16><<<3125, 256>>>(pel2, per2, (const float4*)pZ2, 32, b2a, b2b, (float4*)pH2);

    // ---- chain pass -> shifted conh + fused MH attention dots ----
    chain_norm_shift_dots_kernel<<<6250, 256>>>(pH2, pCONHS, pwml, pwmr, pelm, perm);

    // ---- MH layer: lean input-space agg + split-A GEMM with bias epilogue ----
    aggmhx_kernel<<<6250, 256>>>(pelm, perm, (const float2*)pCONHS, pA2);
    gemm_kernel<4><<<dim3(4, 391), 256>>>(pA2, 320, 64, 256, pB3s, pHM, 256, NN, 128,
                                          pbiasm, 0, 0, 0, nullptr, nullptr, nullptr, nullptr);

    // ---- fused per-head chain pass + cumsum over nodes ----
    dsscan_local_kernel<<<NG2, 128>>>(pHM, out);
    aux_scan_kernel<<<256, 512>>>();
    add_off_kernel<<<(NN*64 + 255)/256, 256>>>(out);
}

// round 16
// speedup vs baseline: 1.0639x; 1.0639x over previous
#include <cuda_runtime.h>

#define NN 50000
#define NE 400000
#define NG2 391       // node groups of 128 for the tail scan

// ---------------- scratch (device globals) ----------------
__device__ float g_Z1[NN*256];
__device__ float g_H1[NN*128];
__device__ float g_Z2[NN*128];
__device__ float g_H2[NN*64];
__device__ float g_CONH[NN*64];
__device__ float g_ZM[(size_t)NN*512];
__device__ float g_HM[NN*256];
__device__ float g_AUX[NG2*256];
__device__ float g_el1[NN], g_er1[NN], g_el2[NN], g_er2[NN];
__device__ float g_elm[NN*4], g_erm[NN*4];
// pre-split interleaved (hi,lo) weights: [Ncol][2K]
__device__ float g_W1s[256*128];
__device__ float g_W2s[128*256];
__device__ float g_W3s[512*128];
__device__ int g_cnt[NN];
__device__ int g_off[NN+1];
__device__ int g_pos[NN];
__device__ int g_csrc[NE];
__device__ int g_gaux[256];

// ---------------- helpers ----------------
__device__ __forceinline__ float lrelu_exp(float v) {
    v = (v >= 0.f) ? v : 0.2f*v;
    return __expf(v);
}
__device__ __forceinline__ float tf32_rna(float x) {
    unsigned r;
    asm("cvt.rna.tf32.f32 %0, %1;" : "=r"(r) : "f"(x));
    return __uint_as_float(r);
}
__device__ __forceinline__ void mma_tf32(float* c,
                                         unsigned a0, unsigned a1, unsigned a2, unsigned a3,
                                         unsigned b0, unsigned b1) {
    asm volatile("mma.sync.aligned.m16n8k8.row.col.f32.tf32.tf32.f32 "
                 "{%0,%1,%2,%3},{%4,%5,%6,%7},{%8,%9},{%0,%1,%2,%3};"
                 : "+f"(c[0]), "+f"(c[1]), "+f"(c[2]), "+f"(c[3])
                 : "r"(a0), "r"(a1), "r"(a2), "r"(a3), "r"(b0), "r"(b1));
}

// ---------------- weight pack: concat a;b AND tf32 hi/lo split (interleaved) ----------------
__global__ void pack_w_kernel(const float* __restrict__ W1a, const float* __restrict__ W1b,
                              const float* __restrict__ W2a, const float* __restrict__ W2b,
                              const float* __restrict__ Wma, const float* __restrict__ Wmb) {
    int i = blockIdx.x*blockDim.x + threadIdx.x;
    if (i < 256*64) {
        int r = i >> 6, k = i & 63;
        float w = (r < 128) ? W1a[i] : W1b[i - 128*64];
        float h = tf32_rna(w);
        g_W1s[r*128 + 2*k] = h; g_W1s[r*128 + 2*k + 1] = w - h;
    }
    if (i < 128*128) {
        int r = i >> 7, k = i & 127;
        float w = (r < 64) ? W2a[i] : W2b[i - 64*128];
        float h = tf32_rna(w);
        g_W2s[r*256 + 2*k] = h; g_W2s[r*256 + 2*k + 1] = w - h;
    }
    if (i < 512*64) {
        int r = i >> 6, k = i & 63;
        float w = (r < 256) ? Wma[i] : Wmb[i - 256*64];
        float h = tf32_rna(w);
        g_W3s[r*128 + 2*k] = h; g_W3s[r*128 + 2*k + 1] = w - h;
    }
}

// ---------------- CSR build ----------------
__global__ void zero_cnt_kernel() {
    int i = blockIdx.x*blockDim.x + threadIdx.x;
    if (i < NN) g_cnt[i] = 0;
}
__global__ void hist_kernel(const int* __restrict__ dst) {
    int e = blockIdx.x*blockDim.x + threadIdx.x;
    if (e < NE) atomicAdd(&g_cnt[dst[e]], 1);
}
__global__ void csr_scan1_kernel() {
    __shared__ int ws[8];
    int g = blockIdx.x, t = threadIdx.x;
    int i = g*256 + t;
    int lane = t & 31, wid = t >> 5;
    int v = (i < NN) ? g_cnt[i] : 0;
    int s = v;
#pragma unroll
    for (int o = 1; o < 32; o <<= 1) {
        int q = __shfl_up_sync(0xffffffffu, s, o);
        if (lane >= o) s += q;
    }
    if (lane == 31) ws[wid] = s;
    __syncthreads();
    if (wid == 0) {
        int w = (lane < 8) ? ws[lane] : 0;
#pragma unroll
        for (int o = 1; o < 8; o <<= 1) {
            int q = __shfl_up_sync(0xffffffffu, w, o);
            if (lane >= o) w += q;
        }
        if (lane < 8) ws[lane] = w;
    }
    __syncthreads();
    int excl = (wid > 0 ? ws[wid-1] : 0) + (s - v);
    if (i < NN) g_off[i] = excl;
    if (t == 0) g_gaux[g] = ws[7];
}
__global__ void csr_scan2_kernel() {
    __shared__ int ws[8];
    int t = threadIdx.x;
    int lane = t & 31, wid = t >> 5;
    int v = (t < 196) ? g_gaux[t] : 0;
    int s = v;
#pragma unroll
    for (int o = 1; o < 32; o <<= 1) {
        int q = __shfl_up_sync(0xffffffffu, s, o);
        if (lane >= o) s += q;
    }
    if (lane == 31) ws[wid] = s;
    __syncthreads();
    if (wid == 0) {
        int w = (lane < 8) ? ws[lane] : 0;
#pragma unroll
        for (int o = 1; o < 8; o <<= 1) {
            int q = __shfl_up_sync(0xffffffffu, w, o);
            if (lane >= o) w += q;
        }
        if (lane < 8) ws[lane] = w;
    }
    __syncthreads();
    int excl = (wid > 0 ? ws[wid-1] : 0) + (s - v);
    if (t < 196) g_gaux[t] = excl;
}
__global__ void csr_apply_kernel() {
    int g = blockIdx.x, t = threadIdx.x;
    int i = g*256 + t;
    if (i < NN) {
        int o = g_off[i] + g_gaux[g];
        g_off[i] = o;
        g_pos[i] = o;
    }
    if (g == 0 && t == 0) g_off[NN] = NE;
}
__global__ void scatter_csr_kernel(const int* __restrict__ src, const int* __restrict__ dst) {
    int e = blockIdx.x*blockDim.x + threadIdx.x;
    if (e >= NE) return;
    int p = atomicAdd(&g_pos[dst[e]], 1);
    g_csrc[p] = src[e];
}

// ---------------- 3xTF32 tensor-core GEMM, conflict-free smem (pad 136 + row swizzle) ----------------
// C[M,Ncol] = A[M,K]*Bsplit^T via mma.sync.m16n8k8.tf32, error-compensated.
// Storage: X[k][ row ^ (8*((k>>2)&3)) ], pad 136 (136k mod 32 = 8k) -> all LDS/STS conflict-free.
// B arrives pre-split (hi,lo interleaved, stride 2K) -> B fill has zero cvt.
// A lo term = a - tf32(a) exactly (MMA truncates lo to tf32 implicitly; error ~2^-22).
#define GKC 16
#define GLDS 136

__global__ __launch_bounds__(256, 2)
void gemm_kernel(const float* __restrict__ A, const float* __restrict__ Bs,
                 float* __restrict__ C, int M, int K, int Ncol,
                 int adimTotal, int hshift, int H,
                 const float* __restrict__ al, const float* __restrict__ ar,
                 float* __restrict__ el, float* __restrict__ er) {
    __shared__ float Ahi[GKC][GLDS];
    __shared__ float Alo[GKC][GLDS];
    __shared__ float Bhi[GKC][GLDS];
    __shared__ float Blo[GKC][GLDS];
    __shared__ float epiel[2][128];
    __shared__ float epier[2][128];

    int tid = threadIdx.x;
    int bm = blockIdx.y * 128;
    int bn = blockIdx.x * 128;
    int w = tid >> 5;
    int lane = tid & 31;
    int warpM = w & 3;        // 4 M-slices of 32 rows
    int warpN = w >> 2;       // 2 N-slices of 64 cols
    int g  = lane >> 2;       // groupID 0..7
    int tg = lane & 3;        // thread-in-group 0..3

    float acc[2][8][4];
#pragma unroll
    for (int mt = 0; mt < 2; mt++)
#pragma unroll
        for (int nt = 0; nt < 8; nt++)
#pragma unroll
            for (int q = 0; q < 4; q++) acc[mt][nt][q] = 0.f;

    int ntiles = K / GKC;
    for (int kt = 0; kt < ntiles; kt++) {
        int koff = kt * GKC;
        // fill: A hi/lo split (4 cvt + 4 sub), B direct copy of pre-split weights.
        // store row' = row ^ (8*tg') where tg' = (k>>2)&3 = i&3
#pragma unroll
        for (int ii = 0; ii < 2; ii++) {
            int i = tid + ii*256;           // 0..511, 4 k-values per item
            int row = i >> 2;
            int tgp = i & 3;
            int k4  = tgp << 2;
            int rsw = row ^ (tgp << 3);     // swizzled store row
            float4 va = make_float4(0.f,0.f,0.f,0.f);
            int gr = bm + row;
            if (gr < M) va = *(const float4*)(A + (size_t)gr*K + koff + k4);
            const float* brow = Bs + (size_t)(bn + row)*2*K + 2*(koff + k4);
            float4 vb0 = *(const float4*)(brow);
            float4 vb1 = *(const float4*)(brow + 4);
            float h;
            h = tf32_rna(va.x); Ahi[k4+0][rsw] = h; Alo[k4+0][rsw] = va.x - h;
            h = tf32_rna(va.y); Ahi[k4+1][rsw] = h; Alo[k4+1][rsw] = va.y - h;
            h = tf32_rna(va.z); Ahi[k4+2][rsw] = h; Alo[k4+2][rsw] = va.z - h;
            h = tf32_rna(va.w); Ahi[k4+3][rsw] = h; Alo[k4+3][rsw] = va.w - h;
            Bhi[k4+0][rsw] = vb0.x; Blo[k4+0][rsw] = vb0.y;
            Bhi[k4+1][rsw] = vb0.z; Blo[k4+1][rsw] = vb0.w;
            Bhi[k4+2][rsw] = vb1.x; Blo[k4+2][rsw] = vb1.y;
            Bhi[k4+3][rsw] = vb1.z; Blo[k4+3][rsw] = vb1.w;
        }
        __syncthreads();

#pragma unroll
        for (int k8 = 0; k8 < GKC/8; k8++) {
            int kb = k8*8;
            int k0 = kb + tg;
            int k1 = kb + tg + 4;
            int sw0 = (((kb >> 2)    ) & 3) << 3;   // row swizzle for k0 (tg-independent)
            int sw1 = (((kb >> 2) + 1) & 3) << 3;   // row swizzle for k1
            unsigned ah[2][4], alr[2][4];
#pragma unroll
            for (int mt = 0; mt < 2; mt++) {
                int rb = warpM*32 + mt*16;
                int r0 = (rb + g)     ^ sw0;
                int r8 = (rb + g + 8) ^ sw0;
                int q0 = (rb + g)     ^ sw1;
                int q8 = (rb + g + 8) ^ sw1;
                ah[mt][0] = __float_as_uint(Ahi[k0][r0]);
                ah[mt][1] = __float_as_uint(Ahi[k0][r8]);
                ah[mt][2] = __float_as_uint(Ahi[k1][q0]);
                ah[mt][3] = __float_as_uint(Ahi[k1][q8]);
                alr[mt][0] = __float_as_uint(Alo[k0][r0]);
                alr[mt][1] = __float_as_uint(Alo[k0][r8]);
                alr[mt][2] = __float_as_uint(Alo[k1][q0]);
                alr[mt][3] = __float_as_uint(Alo[k1][q8]);
            }
#pragma unroll
            for (int nt = 0; nt < 8; nt++) {
                int nb = warpN*64 + nt*8;
                int n0 = (nb + g) ^ sw0;
                int n1 = (nb + g) ^ sw1;
                unsigned bh0 = __float_as_uint(Bhi[k0][n0]);
                unsigned bh1 = __float_as_uint(Bhi[k1][n1]);
                unsigned bl0 = __float_as_uint(Blo[k0][n0]);
                unsigned bl1 = __float_as_uint(Blo[k1][n1]);
#pragma unroll
                for (int mt = 0; mt < 2; mt++) {
                    mma_tf32(acc[mt][nt], ah[mt][0], ah[mt][1], ah[mt][2], ah[mt][3], bh0, bh1);
                    mma_tf32(acc[mt][nt], ah[mt][0], ah[mt][1], ah[mt][2], ah[mt][3], bl0, bl1);
                    mma_tf32(acc[mt][nt], alr[mt][0], alr[mt][1], alr[mt][2], alr[mt][3], bh0, bh1);
                }
            }
        }
        __syncthreads();
    }

    // ---- C store + fused el/er partials ----
    bool awarp = (el != nullptr) && (bn + warpN*64) < adimTotal;
    float pel[2][2] = {{0.f,0.f},{0.f,0.f}};
    float per_[2][2] = {{0.f,0.f},{0.f,0.f}};
#pragma unroll
    for (int mt = 0; mt < 2; mt++) {
        int r0 = bm + warpM*32 + mt*16 + g;
#pragma unroll
        for (int nt = 0; nt < 8; nt++) {
            int gc = bn + warpN*64 + nt*8 + tg*2;
            float c0 = acc[mt][nt][0], c1 = acc[mt][nt][1];
            float c2 = acc[mt][nt][2], c3 = acc[mt][nt][3];
            if (r0 < M)     *(float2*)(C + (size_t)r0*Ncol + gc)     = make_float2(c0, c1);
            if (r0+8 < M)   *(float2*)(C + (size_t)(r0+8)*Ncol + gc) = make_float2(c2, c3);
            if (awarp) {
                float w0 = al[gc], w1 = al[gc+1];
                float u0 = ar[gc], u1 = ar[gc+1];
                pel[mt][0] += c0*w0 + c1*w1;
                pel[mt][1] += c2*w0 + c3*w1;
                per_[mt][0] += c0*u0 + c1*u1;
                per_[mt][1] += c2*u0 + c3*u1;
            }
        }
    }
    if (el != nullptr) {
#pragma unroll
        for (int mt = 0; mt < 2; mt++)
#pragma unroll
            for (int rp = 0; rp < 2; rp++) {
#pragma unroll
                for (int o = 1; o <= 2; o <<= 1) {
                    pel[mt][rp]  += __shfl_xor_sync(0xffffffffu, pel[mt][rp],  o);
                    per_[mt][rp] += __shfl_xor_sync(0xffffffffu, per_[mt][rp], o);
                }
                if (tg == 0) {
                    int row = warpM*32 + mt*16 + g + rp*8;
                    epiel[warpN][row] = pel[mt][rp];
                    epier[warpN][row] = per_[mt][rp];
                }
            }
        __syncthreads();
        if (tid < 128) {
            int row = tid;
            int gr = bm + row;
            if (gr < M) {
                int span = 1 << hshift;
                if (span == 128) {
                    if (bn < adimTotal) {
                        el[gr] = epiel[0][row] + epiel[1][row];
                        er[gr] = epier[0][row] + epier[1][row];
                    }
                } else {  // span == 64
#pragma unroll
                    for (int wn = 0; wn < 2; wn++) {
                        int cb = bn + wn*64;
                        if (cb < adimTotal) {
                            int h = cb >> hshift;
                            el[(size_t)gr*H + h] = epiel[wn][row];
                            er[(size_t)gr*H + h] = epier[wn][row];
                        }
                    }
                }
            }
        }
    }
}

// ---------------- CSR aggregation (H=1) with fused finalize ----------------
template<int D4>
__global__ void agg1_kernel(const float* __restrict__ el, const float* __restrict__ er,
                            const float4* __restrict__ Z4, int ldz4,
                            const float* __restrict__ ba, const float* __restrict__ bb,
                            float4* __restrict__ out4) {
    int t = blockIdx.x*blockDim.x + threadIdx.x;
    int n = t / D4;
    int j = t - n*D4;
    if (n >= NN) return;
    int o0 = g_off[n], o1 = g_off[n+1];
    float ern = er[n];
    float4 acc = make_float4(0.f,0.f,0.f,0.f);
    float den = 0.f;
    for (int p = o0; p < o1; p++) {
        int s = g_csrc[p];
        float ee = lrelu_exp(el[s] + ern);
        den += ee;
        float4 z = Z4[(size_t)s*ldz4 + j];
        acc.x += ee*z.x; acc.y += ee*z.y; acc.z += ee*z.z; acc.w += ee*z.w;
    }
    float inv = (o1 > o0) ? 1.f/den : 0.f;
    float4 b1 = ((const float4*)ba)[j];
    float4 b2 = ((const float4*)bb)[j];
    float4 r;
    r.x = acc.x*inv + b1.x + b2.x;
    r.y = acc.y*inv + b1.y + b2.y;
    r.z = acc.z*inv + b1.z + b2.z;
    r.w = acc.w*inv + b1.w + b2.w;
    if (n > 0) {
        float4 zb = Z4[(size_t)(n-1)*ldz4 + D4 + j];
        r.x += zb.x; r.y += zb.y; r.z += zb.z; r.w += zb.w;
    }
    out4[(size_t)n*D4 + j] = make_float4(0.5f*r.x, 0.5f*r.y, 0.5f*r.z, 0.5f*r.w);
}

// ---------------- CSR aggregation (H=4, D=64) with fused finalize ----------------
__global__ void aggmh_kernel(const float* __restrict__ el, const float* __restrict__ er,
                             const float4* __restrict__ Z4,
                             const float* __restrict__ ba, const float* __restrict__ bb,
                             float4* __restrict__ out4) {
    int w = (blockIdx.x*blockDim.x + threadIdx.x) >> 5;
    int lane = threadIdx.x & 31;
    if (w >= NN) return;
    int n = w;
    int h0 = lane >> 4;
    int h1 = h0 + 2;
    float er0 = er[n*4 + h0], er1 = er[n*4 + h1];
    int o0 = g_off[n], o1 = g_off[n+1];
    float4 acc0 = make_float4(0.f,0.f,0.f,0.f);
    float4 acc1 = make_float4(0.f,0.f,0.f,0.f);
    float den0 = 0.f, den1 = 0.f;
    for (int p = o0; p < o1; p++) {
        int s = g_csrc[p];
        float e0 = lrelu_exp(el[s*4 + h0] + er0);
        float e1 = lrelu_exp(el[s*4 + h1] + er1);
        den0 += e0; den1 += e1;
        size_t zb = (size_t)s*128;
        float4 z0 = Z4[zb + lane];
        float4 z1 = Z4[zb + 32 + lane];
        acc0.x += e0*z0.x; acc0.y += e0*z0.y; acc0.z += e0*z0.z; acc0.w += e0*z0.w;
        acc1.x += e1*z1.x; acc1.y += e1*z1.y; acc1.z += e1*z1.z; acc1.w += e1*z1.w;
    }
    float i0 = (o1 > o0) ? 1.f/den0 : 0.f;
    float i1 = (o1 > o0) ? 1.f/den1 : 0.f;
    float4 ba0 = ((const float4*)ba)[lane],    bb0 = ((const float4*)bb)[lane];
    float4 ba1 = ((const float4*)ba)[32+lane], bb1 = ((const float4*)bb)[32+lane];
    float4 r0, r1;
    r0.x = acc0.x*i0 + ba0.x + bb0.x; r0.y = acc0.y*i0 + ba0.y + bb0.y;
    r0.z = acc0.z*i0 + ba0.z + bb0.z; r0.w = acc0.w*i0 + ba0.w + bb0.w;
    r1.x = acc1.x*i1 + ba1.x + bb1.x; r1.y = acc1.y*i1 + ba1.y + bb1.y;
    r1.z = acc1.z*i1 + ba1.z + bb1.z; r1.w = acc1.w*i1 + ba1.w + bb1.w;
    if (n > 0) {
        size_t pb = (size_t)(n-1)*128;
        float4 zb0 = Z4[pb + 64 + lane];
        float4 zb1 = Z4[pb + 96 + lane];
        r0.x += zb0.x; r0.y += zb0.y; r0.z += zb0.z; r0.w += zb0.w;
        r1.x += zb1.x; r1.y += zb1.y; r1.z += zb1.z; r1.w += zb1.w;
    }
    out4[(size_t)n*64 + lane]      = make_float4(0.5f*r0.x, 0.5f*r0.y, 0.5f*r0.z, 0.5f*r0.w);
    out4[(size_t)n*64 + 32 + lane] = make_float4(0.5f*r1.x, 0.5f*r1.y, 0.5f*r1.z, 0.5f*r1.w);
}

// ---------------- chain pass (H=1): normalize(h[n-1]-h[n]) ----------------
__global__ void chain_norm_kernel(const float* __restrict__ Hin, float* __restrict__ out) {
    int w = (blockIdx.x*blockDim.x + threadIdx.x) >> 5;
    int lane = threadIdx.x & 31;
    if (w >= NN) return;
    int n = w;
    int base = n*64 + lane*2;
    float d0 = 0.f, d1 = 0.f;
    if (n > 0) {
        d0 = Hin[base - 64]     - Hin[base];
        d1 = Hin[base - 64 + 1] - Hin[base + 1];
    }
    float ss = d0*d0 + d1*d1;
#pragma unroll
    for (int o = 16; o; o >>= 1) ss += __shfl_xor_sync(0xffffffffu, ss, o);
    float inv = 1.f/(sqrtf(ss) + 1e-7f);
    out[base]   = d0*inv;
    out[base+1] = d1*inv;
}

// ---------------- fused tail ----------------
__global__ __launch_bounds__(128)
void dsscan_local_kernel(const float* __restrict__ HM, float* __restrict__ out) {
    int g = blockIdx.x;
    int t = threadIdx.x, wid = t >> 5, lane = t & 31;
    int c = wid*64 + lane*2;
    int start = g*128;
    int end = min(start+128, NN);
    const float2* H2p = (const float2*)HM;
    float2* out2 = (float2*)out;
    int ci = c >> 1;
    float2 prev = (start > 0) ? H2p[(size_t)(start-1)*128 + ci] : make_float2(0.f,0.f);
    float2 cur  = H2p[(size_t)start*128 + ci];
    float rx = 0.f, ry = 0.f;
    for (int n = start; n < end; n++) {
        float2 nxt = (n+1 < end) ? H2p[(size_t)(n+1)*128 + ci] : make_float2(0.f,0.f);
        float d0 = 0.f, d1 = 0.f;
        if (n > 0) { d0 = prev.x - cur.x; d1 = prev.y - cur.y; }
        float ss = d0*d0 + d1*d1;
#pragma unroll
        for (int o = 16; o; o >>= 1) ss += __shfl_xor_sync(0xffffffffu, ss, o);
        float inv = 1.f/(sqrtf(ss) + 1e-7f);
        rx += d0*inv; ry += d1*inv;
        out2[(size_t)n*128 + ci] = make_float2(rx, ry);
        prev = cur; cur = nxt;
    }
    ((float2*)g_AUX)[g*128 + ci] = make_float2(rx, ry);
}
__global__ void aux_scan_kernel() {
    __shared__ float ws[16];
    int c = blockIdx.x;
    int t = threadIdx.x;
    int lane = t & 31, wid = t >> 5;
    float v = (t < NG2) ? g_AUX[t*256 + c] : 0.f;
    float s = v;
#pragma unroll
    for (int o = 1; o < 32; o <<= 1) {
        float q = __shfl_up_sync(0xffffffffu, s, o);
        if (lane >= o) s += q;
    }
    if (lane == 31) ws[wid] = s;
    __syncthreads();
    if (wid == 0) {
        float w = (lane < 16) ? ws[lane] : 0.f;
#pragma unroll
        for (int o = 1; o < 16; o <<= 1) {
            float q = __shfl_up_sync(0xffffffffu, w, o);
            if (lane >= o) w += q;
        }
        if (lane < 16) ws[lane] = w;
    }
    __syncthreads();
    float excl = (wid > 0 ? ws[wid-1] : 0.f) + (s - v);
    if (t < NG2) g_AUX[t*256 + c] = excl;
}
__global__ void add_off_kernel(float* __restrict__ out) {
    int i = blockIdx.x*blockDim.x + threadIdx.x;
    if (i >= NN*64) return;
    int n = i >> 6, c4 = i & 63;
    int g = n >> 7;
    float4 o = ((float4*)out)[i];
    float4 a = ((const float4*)g_AUX)[g*64 + c4];
    o.x += a.x; o.y += a.y; o.z += a.z; o.w += a.w;
    ((float4*)out)[i] = o;
}

// ---------------- host orchestration ----------------
extern "C" void kernel_launch(void* const* d_in, const int* in_sizes, int n_in,
                              void* d_out, int out_size) {
    const float* x    = (const float*)d_in[0];
    const int*   src0 = (const int*)d_in[1];
    const int*   dst0 = (const int*)d_in[2];
    const float* W1a  = (const float*)d_in[5];
    const float* al1a = (const float*)d_in[6];
    const float* ar1a = (const float*)d_in[7];
    const float* b1a  = (const float*)d_in[8];
    const float* W1b  = (const float*)d_in[9];
    const float* b1b  = (const float*)d_in[12];
    const float* W2a  = (const float*)d_in[13];
    const float* al2a = (const float*)d_in[14];
    const float* ar2a = (const float*)d_in[15];
    const float* b2a  = (const float*)d_in[16];
    const float* W2b  = (const float*)d_in[17];
    const float* b2b  = (const float*)d_in[20];
    const float* Wma  = (const float*)d_in[21];
    const float* alma = (const float*)d_in[22];
    const float* arma = (const float*)d_in[23];
    const float* bma  = (const float*)d_in[24];
    const float* Wmb  = (const float*)d_in[25];
    const float* bmb  = (const float*)d_in[28];
    float* out = (float*)d_out;

    float *pZ1,*pH1,*pZ2,*pH2,*pCONH,*pZM,*pHM;
    float *pel1,*per1,*pel2,*per2,*pelm,*perm;
    float *pW1s,*pW2s,*pW3s;
    cudaGetSymbolAddress((void**)&pZ1,  g_Z1);
    cudaGetSymbolAddress((void**)&pH1,  g_H1);
    cudaGetSymbolAddress((void**)&pZ2,  g_Z2);
    cudaGetSymbolAddress((void**)&pH2,  g_H2);
    cudaGetSymbolAddress((void**)&pCONH,g_CONH);
    cudaGetSymbolAddress((void**)&pZM,  g_ZM);
    cudaGetSymbolAddress((void**)&pHM,  g_HM);
    cudaGetSymbolAddress((void**)&pel1, g_el1);
    cudaGetSymbolAddress((void**)&per1, g_er1);
    cudaGetSymbolAddress((void**)&pel2, g_el2);
    cudaGetSymbolAddress((void**)&per2, g_er2);
    cudaGetSymbolAddress((void**)&pelm, g_elm);
    cudaGetSymbolAddress((void**)&perm, g_erm);
    cudaGetSymbolAddress((void**)&pW1s, g_W1s);
    cudaGetSymbolAddress((void**)&pW2s, g_W2s);
    cudaGetSymbolAddress((void**)&pW3s, g_W3s);

    // launch order: ncu capture window (4th launch) hits gemm1
    pack_w_kernel<<<128, 256>>>(W1a, W1b, W2a, W2b, Wma, Wmb);
    zero_cnt_kernel<<<(NN + 255)/256, 256>>>();
    hist_kernel<<<(NE + 255)/256, 256>>>(dst0);

    // ---- layer 1 GEMM (4th launch -> profiled) ----
    gemm_kernel<<<dim3(2, 391), 256>>>(x, pW1s, pZ1, NN, 64, 256,
                                       128, 7, 1, al1a, ar1a, pel1, per1);

    // ---- CSR build (independent of GEMM1) ----
    csr_scan1_kernel<<<196, 256>>>();
    csr_scan2_kernel<<<1, 256>>>();
    csr_apply_kernel<<<196, 256>>>();
    scatter_csr_kernel<<<(NE + 255)/256, 256>>>(src0, dst0);

    agg1_kernel<32><<<6250, 256>>>(pel1, per1, (const float4*)pZ1, 64, b1a, b1b, (float4*)pH1);

    // ---- layer 2 ----
    gemm_kernel<<<dim3(1, 391), 256>>>(pH1, pW2s, pZ2, NN, 128, 128,
                                       64, 6, 1, al2a, ar2a, pel2, per2);
    agg1_kernel<16><<<3125, 256>>>(pel2, per2, (const float4*)pZ2, 32, b2a, b2b, (float4*)pH2);

    // ---- chain pass -> conh ----
    chain_norm_kernel<<<6250, 256>>>(pH2, pCONH);

    // ---- layer MH ----
    gemm_kernel<<<dim3(4, 391), 256>>>(pCONH, pW3s, pZM, NN, 64, 512,
                                       256, 6, 4, alma, arma, pelm, perm);
    aggmh_kernel<<<6250, 256>>>(pelm, perm, (const float4*)pZM, bma, bmb, (float4*)pHM);

    // ---- fused per-head chain pass + cumsum over nodes ----
    dsscan_local_kernel<<<NG2, 128>>>(pHM, out);
    aux_scan_kernel<<<256, 512>>>();
    add_off_kernel<<<(NN*64 + 255)/256, 256>>>(out);
}